// round 12
// baseline (speedup 1.0000x reference)
#include <cuda_runtime.h>
#include <cuda_fp16.h>
#include <cstdint>

#define B_    128
#define LQ_   512
#define LD_   512
#define DIM   128
#define TM    128            // q rows per CTA
#define TN    64             // doc rows per chunk
#define NCHUNK (LD_ / TN)    // 8
#define NTHREADS 256

// ---- global scratch: pre-converted fp16 D + exact fp32 row norms ----
__device__ __half g_Dh[B_ * LD_ * DIM];           // 16 MB
__device__ float  g_Dsq[B_ * LD_];                // 256 KB

// ---- kernel-2 smem layout (bytes) ----
#define SM_QS    0                      // 128x128 fp16 swizzled = 32768
#define SM_DS0   32768                  // fp16 chunk buf 0 (16384)
#define SM_DS1   49152                  // fp16 chunk buf 1 (16384)
#define SM_DSQ   65536                  // 512 floats = 2048
#define SM_QSQ   67584                  // 128 floats = 512
#define SM_MAX   68096                  // 128*2 floats = 1024
#define SM_RED   69120                  // 8 floats
#define SMEM_TOTAL (SM_RED + 64)        // 69184

__device__ __forceinline__ uint32_t smem_u32(const void* p) {
    uint32_t a;
    asm("{ .reg .u64 t; cvta.to.shared.u64 t, %1; cvt.u32.u64 %0, t; }" : "=r"(a) : "l"(p));
    return a;
}

__device__ __forceinline__ void ldmatrix_x4(uint32_t& r0, uint32_t& r1,
                                            uint32_t& r2, uint32_t& r3, uint32_t addr) {
    asm volatile("ldmatrix.sync.aligned.m8n8.x4.shared.b16 {%0,%1,%2,%3}, [%4];"
                 : "=r"(r0), "=r"(r1), "=r"(r2), "=r"(r3) : "r"(addr));
}

// f16 in / f16 acc
__device__ __forceinline__ void mma_16816_f16(uint32_t& c0, uint32_t& c1,
                                              uint32_t a0, uint32_t a1, uint32_t a2, uint32_t a3,
                                              uint32_t b0, uint32_t b1) {
    asm volatile("mma.sync.aligned.m16n8k16.row.col.f16.f16.f16.f16 "
                 "{%0,%1}, {%2,%3,%4,%5}, {%6,%7}, {%0,%1};"
                 : "+r"(c0), "+r"(c1)
                 : "r"(a0), "r"(a1), "r"(a2), "r"(a3), "r"(b0), "r"(b1));
}

__device__ __forceinline__ void cp_async16(uint32_t dst, const void* src) {
    asm volatile("cp.async.cg.shared.global [%0], [%1], 16;" :: "r"(dst), "l"(src));
}
__device__ __forceinline__ void cp_commit() {
    asm volatile("cp.async.commit_group;" ::: "memory");
}
template <int N>
__device__ __forceinline__ void cp_wait() {
    asm volatile("cp.async.wait_group %0;" :: "n"(N) : "memory");
}

// ================= kernel 1: D fp32 -> fp16 + exact row norms (+ zero out) ====
__global__ void __launch_bounds__(NTHREADS)
convert_d_kernel(const float* __restrict__ Dg, float* __restrict__ out) {
    const int tid = threadIdx.x;
    const int w = tid >> 5, l = tid & 31;
    const int rsub = l >> 3;
    const int piece = l & 7;

    if (blockIdx.x == 0 && tid < B_) out[tid] = 0.0f;

    #pragma unroll
    for (int pass = 0; pass < 4; pass++) {
        int row = blockIdx.x * 128 + w * 16 + pass * 4 + rsub;
        const float4* src = reinterpret_cast<const float4*>(Dg + (size_t)row * DIM);
        float4 v[4];
        #pragma unroll
        for (int i = 0; i < 4; i++) v[i] = src[piece + 8 * i];

        float s = 0.0f;
        #pragma unroll
        for (int i = 0; i < 4; i++)
            s += v[i].x * v[i].x + v[i].y * v[i].y + v[i].z * v[i].z + v[i].w * v[i].w;
        s += __shfl_xor_sync(0xffffffffu, s, 1);
        s += __shfl_xor_sync(0xffffffffu, s, 2);
        s += __shfl_xor_sync(0xffffffffu, s, 4);
        if (piece == 0) g_Dsq[row] = s;

        uint2* drow = reinterpret_cast<uint2*>(g_Dh + (size_t)row * DIM);
        #pragma unroll
        for (int i = 0; i < 4; i++) {
            __half2 p0 = __floats2half2_rn(v[i].x, v[i].y);
            __half2 p1 = __floats2half2_rn(v[i].z, v[i].w);
            drow[piece + 8 * i] = make_uint2(*reinterpret_cast<uint32_t*>(&p0),
                                             *reinterpret_cast<uint32_t*>(&p1));
        }
    }
}

// ================= kernel 2: GEMM + fused max/sum epilogue =================
__global__ void __launch_bounds__(NTHREADS, 2)
colbert_mma_kernel(const float* __restrict__ Qg, float* __restrict__ out) {
    extern __shared__ char smem[];
    const uint32_t sb = smem_u32(smem);
    float* dsq_s  = reinterpret_cast<float*>(smem + SM_DSQ);
    float* qsq    = reinterpret_cast<float*>(smem + SM_QSQ);
    float* maxbuf = reinterpret_cast<float*>(smem + SM_MAX);
    float* red    = reinterpret_cast<float*>(smem + SM_RED);

    const int tid = threadIdx.x;
    const int w = tid >> 5, l = tid & 31;
    const int wm = w >> 1;               // 0..3 : 32-row M block
    const int wn = w & 1;                // 0..1 : 32-col N block

    const int b  = blockIdx.x >> 2;
    const int qt = blockIdx.x & 3;
    const float* Qb = Qg + ((size_t)(b * LQ_ + qt * TM)) * DIM;
    const __half* Dh_b = g_Dh + (size_t)b * LD_ * DIM;

    // ---- issue cp.async for chunks 0 and 1 (fp16, swizzled dst) ----
    {
        #pragma unroll
        for (int cbuf = 0; cbuf < 2; cbuf++) {
            const char* src_base = reinterpret_cast<const char*>(Dh_b + (size_t)cbuf * TN * DIM);
            uint32_t dst_base = sb + SM_DS0 + (uint32_t)(cbuf * 16384);
            #pragma unroll
            for (int j = 0; j < 4; j++) {
                int idx = tid + 256 * j;
                int r = idx >> 4, cc = idx & 15;
                cp_async16(dst_base + (uint32_t)(r * 256 + (((cc ^ (r & 7)) << 4))),
                           src_base + r * 256 + cc * 16);
            }
            cp_commit();
        }
    }

    // ---- convert Q tile fp32 -> fp16(2*q) swizzled smem + qsq (overlapped) ----
    {
        char* qs = smem + SM_QS;
        #pragma unroll
        for (int j = 0; j < TM / 8; j++) {
            int row = j * 8 + w;
            float4 v = reinterpret_cast<const float4*>(Qb)[row * 32 + l];
            float s = v.x * v.x + v.y * v.y + v.z * v.z + v.w * v.w;
            #pragma unroll
            for (int o = 16; o > 0; o >>= 1) s += __shfl_xor_sync(0xffffffffu, s, o);
            if (l == 0) qsq[row] = s;
            __half2 p0 = __floats2half2_rn(2.0f * v.x, 2.0f * v.y);
            __half2 p1 = __floats2half2_rn(2.0f * v.z, 2.0f * v.w);
            uint2 pk = make_uint2(*reinterpret_cast<uint32_t*>(&p0),
                                  *reinterpret_cast<uint32_t*>(&p1));
            uint32_t addr = (uint32_t)(row * 256 + (((l >> 1) ^ (row & 7)) << 4) + ((l & 1) << 3));
            *reinterpret_cast<uint2*>(qs + addr) = pk;
        }
    }
    // ---- whole-batch doc norms into smem (512 floats) ----
    {
        const float* src = g_Dsq + b * LD_;
        dsq_s[tid] = src[tid];
        dsq_s[tid + 256] = src[tid + 256];
    }

    // ---- ldmatrix lane addressing (validated structure) ----
    const int jj = l >> 3;
    const int rr = l & 7;
    const int arow = wm * 32 + ((jj & 1) << 3) + rr;
    const int achunk_off = jj >> 1;
    const int asw = arow & 7;
    const int brow = wn * 32 + ((jj >> 1) << 3) + rr;
    const int bchunk_off = jj & 1;
    const int bsw = brow & 7;

    const int tg = l >> 2;
    const int tc = l & 3;

    __syncthreads();   // Q smem fully written (before A-fragment loads)

    // ---- load ALL Q fragments into registers ONCE: a[mt][k][4] = 64 regs ----
    uint32_t a[2][8][4];
    #pragma unroll
    for (int mt = 0; mt < 2; mt++)
        #pragma unroll
        for (int k = 0; k < 8; k++) {
            uint32_t addr = sb + SM_QS + (uint32_t)((arow + mt * 16) * 256
                          + (((k * 2 + achunk_off) ^ asw) << 4));
            ldmatrix_x4(a[mt][k][0], a[mt][k][1], a[mt][k][2], a[mt][k][3], addr);
        }

    float rlo[2], rhi[2];
    #pragma unroll
    for (int mt = 0; mt < 2; mt++) { rlo[mt] = -3.402823e38f; rhi[mt] = -3.402823e38f; }

    #pragma unroll
    for (int c = 0; c < NCHUNK; c++) {
        if (c < NCHUNK - 1) cp_wait<1>(); else cp_wait<0>();
        __syncthreads();   // chunk c visible to all

        const uint32_t ds_cur_u = sb + SM_DS0 + (uint32_t)((c & 1) * 16384);

        // f16 accumulators: 2 regs per mma tile
        uint32_t acc[2][4][2];
        #pragma unroll
        for (int mt = 0; mt < 2; mt++)
            #pragma unroll
            for (int nt = 0; nt < 4; nt++) { acc[mt][nt][0] = 0u; acc[mt][nt][1] = 0u; }

        // ---- B-fragment double buffer: load k+1 while running MMAs of k ----
        uint32_t bf[2][4][2];
        #pragma unroll
        for (int p = 0; p < 2; p++) {   // prologue k=0
            uint32_t addr = ds_cur_u + (uint32_t)((brow + p * 16) * 256
                          + ((bchunk_off ^ bsw) << 4));
            uint32_t r0, r1, r2, r3;
            ldmatrix_x4(r0, r1, r2, r3, addr);
            bf[0][p * 2 + 0][0] = r0; bf[0][p * 2 + 0][1] = r1;
            bf[0][p * 2 + 1][0] = r2; bf[0][p * 2 + 1][1] = r3;
        }

        #pragma unroll
        for (int k = 0; k < 8; k++) {
            const int cur = k & 1, nxt = cur ^ 1;
            if (k < 7) {
                #pragma unroll
                for (int p = 0; p < 2; p++) {
                    uint32_t addr = ds_cur_u + (uint32_t)((brow + p * 16) * 256
                                  + ((((k + 1) * 2 + bchunk_off) ^ bsw) << 4));
                    uint32_t r0, r1, r2, r3;
                    ldmatrix_x4(r0, r1, r2, r3, addr);
                    bf[nxt][p * 2 + 0][0] = r0; bf[nxt][p * 2 + 0][1] = r1;
                    bf[nxt][p * 2 + 1][0] = r2; bf[nxt][p * 2 + 1][1] = r3;
                }
            }
            #pragma unroll
            for (int mt = 0; mt < 2; mt++)
                #pragma unroll
                for (int nt = 0; nt < 4; nt++)
                    mma_16816_f16(acc[mt][nt][0], acc[mt][nt][1],
                                  a[mt][k][0], a[mt][k][1], a[mt][k][2], a[mt][k][3],
                                  bf[cur][nt][0], bf[cur][nt][1]);
        }

        // ---- refill this buffer with chunk c+2 ASAP (overlaps epilogue) ----
        if (c < NCHUNK - 2) {
            __syncthreads();   // all warps done with ldmatrix on this buffer
            const char* src_base = reinterpret_cast<const char*>(Dh_b + (size_t)(c + 2) * TN * DIM);
            uint32_t dst_base = sb + SM_DS0 + (uint32_t)((c & 1) * 16384);
            #pragma unroll
            for (int j = 0; j < 4; j++) {
                int idx = tid + 256 * j;
                int r = idx >> 4, cc = idx & 15;
                cp_async16(dst_base + (uint32_t)(r * 256 + (((cc ^ (r & 7)) << 4))),
                           src_base + r * 256 + cc * 16);
            }
            cp_commit();
        }

        // ---- fused epilogue: neg_dist = (2q).d - d^2 ; running max ----
        #pragma unroll
        for (int nt = 0; nt < 4; nt++) {
            float2 ds2 = *reinterpret_cast<float2*>(&dsq_s[c * TN + wn * 32 + nt * 8 + tc * 2]);
            #pragma unroll
            for (int mt = 0; mt < 2; mt++) {
                float2 lo = __half22float2(*reinterpret_cast<__half2*>(&acc[mt][nt][0]));
                float2 hi = __half22float2(*reinterpret_cast<__half2*>(&acc[mt][nt][1]));
                rlo[mt] = fmaxf(rlo[mt], fmaxf(lo.x - ds2.x, lo.y - ds2.y));
                rhi[mt] = fmaxf(rhi[mt], fmaxf(hi.x - ds2.x, hi.y - ds2.y));
            }
        }
    }

    // ---- cross-lane max (cols in lane bits 0..1) ----
    #pragma unroll
    for (int mt = 0; mt < 2; mt++) {
        rlo[mt] = fmaxf(rlo[mt], __shfl_xor_sync(0xffffffffu, rlo[mt], 1));
        rlo[mt] = fmaxf(rlo[mt], __shfl_xor_sync(0xffffffffu, rlo[mt], 2));
        rhi[mt] = fmaxf(rhi[mt], __shfl_xor_sync(0xffffffffu, rhi[mt], 1));
        rhi[mt] = fmaxf(rhi[mt], __shfl_xor_sync(0xffffffffu, rhi[mt], 2));
    }
    if (tc == 0) {
        #pragma unroll
        for (int mt = 0; mt < 2; mt++) {
            maxbuf[(wm * 32 + mt * 16 + tg) * 2 + wn]     = rlo[mt];
            maxbuf[(wm * 32 + mt * 16 + 8 + tg) * 2 + wn] = rhi[mt];
        }
    }
    __syncthreads();

    // ---- row max across 2 warp-cols, subtract ||q||^2, block sum ----
    float val = 0.0f;
    if (tid < TM) {
        float2 m2 = *reinterpret_cast<float2*>(&maxbuf[tid * 2]);
        val = fmaxf(m2.x, m2.y) - qsq[tid];
    }
    #pragma unroll
    for (int o = 16; o > 0; o >>= 1) val += __shfl_xor_sync(0xffffffffu, val, o);
    if (l == 0) red[w] = val;
    __syncthreads();
    if (tid == 0) {
        float s = 0.0f;
        #pragma unroll
        for (int i = 0; i < 8; i++) s += red[i];
        atomicAdd(&out[b], s);
    }
}

extern "C" void kernel_launch(void* const* d_in, const int* in_sizes, int n_in,
                              void* d_out, int out_size) {
    const float* Qg = (const float*)d_in[0];
    const float* Dg = (const float*)d_in[1];
    float* out = (float*)d_out;

    static int attr_set = 0;
    if (!attr_set) {
        cudaFuncSetAttribute(colbert_mma_kernel,
                             cudaFuncAttributeMaxDynamicSharedMemorySize, SMEM_TOTAL);
        attr_set = 1;
    }

    convert_d_kernel<<<(B_ * LD_) / 128, NTHREADS>>>(Dg, out);
    colbert_mma_kernel<<<B_ * (LQ_ / TM), NTHREADS, SMEM_TOTAL>>>(Qg, out);
}

// round 13
// speedup vs baseline: 1.0912x; 1.0912x over previous
#include <cuda_runtime.h>
#include <cstdint>

#define B_    128
#define LQ_   512
#define LD_   512
#define DIM   128
#define TM    128            // q rows per CTA
#define TN    64             // doc rows per chunk
#define NCHUNK (LD_ / TN)    // 8
#define NTHREADS 256

// ---- global scratch: int8-quantized D + exact fp32 row norms + dequant scales ----
__device__ int8_t g_Dq[B_ * LD_ * DIM];           // 8 MB
__device__ float  g_Dsq[B_ * LD_];                // 256 KB
__device__ float  g_Ddf[B_ * LD_];                // dequant factor maxabs/127

// ---- kernel-2 smem layout (bytes) ----
#define SM_QS    0                      // 128x128 int8 swizzled = 16384
#define SM_DS0   16384                  // int8 chunk buf 0 (8192)
#define SM_DS1   24576                  // int8 chunk buf 1 (8192)
#define SM_DSQ   32768                  // 512 floats = 2048
#define SM_DDF   34816                  // 512 floats = 2048
#define SM_QSQ   36864                  // 128 floats = 512
#define SM_QF    37376                  // 128 floats = 512
#define SM_MAX   37888                  // 128*2 floats = 1024
#define SM_RED   38912                  // 8 floats
#define SMEM_TOTAL (SM_RED + 64)        // 38976

__device__ __forceinline__ uint32_t smem_u32(const void* p) {
    uint32_t a;
    asm("{ .reg .u64 t; cvta.to.shared.u64 t, %1; cvt.u32.u64 %0, t; }" : "=r"(a) : "l"(p));
    return a;
}

__device__ __forceinline__ void ldmatrix_x4(uint32_t& r0, uint32_t& r1,
                                            uint32_t& r2, uint32_t& r3, uint32_t addr) {
    asm volatile("ldmatrix.sync.aligned.m8n8.x4.shared.b16 {%0,%1,%2,%3}, [%4];"
                 : "=r"(r0), "=r"(r1), "=r"(r2), "=r"(r3) : "r"(addr));
}

// s8 x s8 -> s32, K=32 per instruction (exact integer accumulate)
__device__ __forceinline__ void mma_16832_s8(int& c0, int& c1, int& c2, int& c3,
                                             uint32_t a0, uint32_t a1, uint32_t a2, uint32_t a3,
                                             uint32_t b0, uint32_t b1) {
    asm volatile("mma.sync.aligned.m16n8k32.row.col.s32.s8.s8.s32 "
                 "{%0,%1,%2,%3}, {%4,%5,%6,%7}, {%8,%9}, {%0,%1,%2,%3};"
                 : "+r"(c0), "+r"(c1), "+r"(c2), "+r"(c3)
                 : "r"(a0), "r"(a1), "r"(a2), "r"(a3), "r"(b0), "r"(b1));
}

__device__ __forceinline__ void cp_async16(uint32_t dst, const void* src) {
    asm volatile("cp.async.cg.shared.global [%0], [%1], 16;" :: "r"(dst), "l"(src));
}
__device__ __forceinline__ void cp_commit() {
    asm volatile("cp.async.commit_group;" ::: "memory");
}
template <int N>
__device__ __forceinline__ void cp_wait() {
    asm volatile("cp.async.wait_group %0;" :: "n"(N) : "memory");
}

__device__ __forceinline__ uint32_t pack4(float4 v, float S) {
    int a = __float2int_rn(v.x * S), b = __float2int_rn(v.y * S);
    int c = __float2int_rn(v.z * S), d = __float2int_rn(v.w * S);
    return (uint32_t)(a & 0xff) | ((uint32_t)(b & 0xff) << 8)
         | ((uint32_t)(c & 0xff) << 16) | ((uint32_t)(d & 0xff) << 24);
}

// ============ kernel 1: D fp32 -> int8 (per-row scale) + norms (+ zero out) ====
__global__ void __launch_bounds__(NTHREADS)
convert_d_kernel(const float* __restrict__ Dg, float* __restrict__ out) {
    const int tid = threadIdx.x;
    const int w = tid >> 5, l = tid & 31;
    const int rsub = l >> 3;
    const int piece = l & 7;

    if (blockIdx.x == 0 && tid < B_) out[tid] = 0.0f;

    #pragma unroll
    for (int pass = 0; pass < 4; pass++) {
        int row = blockIdx.x * 128 + w * 16 + pass * 4 + rsub;
        const float4* src = reinterpret_cast<const float4*>(Dg + (size_t)row * DIM);
        float4 v[4];
        #pragma unroll
        for (int i = 0; i < 4; i++) v[i] = src[piece + 8 * i];

        float s = 0.0f, m = 0.0f;
        #pragma unroll
        for (int i = 0; i < 4; i++) {
            s += v[i].x * v[i].x + v[i].y * v[i].y + v[i].z * v[i].z + v[i].w * v[i].w;
            m = fmaxf(m, fmaxf(fmaxf(fabsf(v[i].x), fabsf(v[i].y)),
                               fmaxf(fabsf(v[i].z), fabsf(v[i].w))));
        }
        #pragma unroll
        for (int o = 4; o > 0; o >>= 1) {
            s += __shfl_xor_sync(0xffffffffu, s, o);
            m = fmaxf(m, __shfl_xor_sync(0xffffffffu, m, o));
        }
        m = fmaxf(m, 1e-20f);
        if (piece == 0) {
            g_Dsq[row] = s;
            g_Ddf[row] = m * (1.0f / 127.0f);
        }
        float S = 127.0f / m;
        uint32_t* qrow = reinterpret_cast<uint32_t*>(g_Dq + (size_t)row * DIM);
        #pragma unroll
        for (int i = 0; i < 4; i++) qrow[piece + 8 * i] = pack4(v[i], S);
    }
}

// ============ kernel 2: int8 IMMA GEMM + fused dequant/max/sum epilogue =========
__global__ void __launch_bounds__(NTHREADS, 2)
colbert_mma_kernel(const float* __restrict__ Qg, float* __restrict__ out) {
    extern __shared__ char smem[];
    const uint32_t sb = smem_u32(smem);
    float* dsq_s  = reinterpret_cast<float*>(smem + SM_DSQ);
    float* ddf_s  = reinterpret_cast<float*>(smem + SM_DDF);
    float* qsq    = reinterpret_cast<float*>(smem + SM_QSQ);
    float* qf_s   = reinterpret_cast<float*>(smem + SM_QF);
    float* maxbuf = reinterpret_cast<float*>(smem + SM_MAX);
    float* red    = reinterpret_cast<float*>(smem + SM_RED);

    const int tid = threadIdx.x;
    const int w = tid >> 5, l = tid & 31;
    const int wm = w >> 1;               // 0..3 : 32-row M block
    const int wn = w & 1;                // 0..1 : 32-col N block

    const int b  = blockIdx.x >> 2;
    const int qt = blockIdx.x & 3;
    const float* Qb = Qg + ((size_t)(b * LQ_ + qt * TM)) * DIM;
    const int8_t* Dq_b = g_Dq + (size_t)b * LD_ * DIM;

    // ---- issue cp.async for chunks 0 and 1 (int8, swizzled dst; 512 granules/chunk) ----
    {
        #pragma unroll
        for (int cbuf = 0; cbuf < 2; cbuf++) {
            const char* src_base = reinterpret_cast<const char*>(Dq_b + (size_t)cbuf * TN * DIM);
            uint32_t dst_base = sb + SM_DS0 + (uint32_t)(cbuf * 8192);
            #pragma unroll
            for (int j = 0; j < 2; j++) {
                int idx = tid + 256 * j;
                int r = idx >> 3, cc = idx & 7;
                cp_async16(dst_base + (uint32_t)(r * 128 + (((cc ^ (r & 7)) << 4))),
                           src_base + r * 128 + cc * 16);
            }
            cp_commit();
        }
    }

    // ---- convert Q tile fp32 -> int8 (per-row scale) swizzled smem + qsq/qf ----
    {
        #pragma unroll
        for (int j = 0; j < TM / 8; j++) {
            int row = j * 8 + w;
            float4 v = reinterpret_cast<const float4*>(Qb)[row * 32 + l];
            float s = v.x * v.x + v.y * v.y + v.z * v.z + v.w * v.w;
            float m = fmaxf(fmaxf(fabsf(v.x), fabsf(v.y)), fmaxf(fabsf(v.z), fabsf(v.w)));
            #pragma unroll
            for (int o = 16; o > 0; o >>= 1) {
                s += __shfl_xor_sync(0xffffffffu, s, o);
                m = fmaxf(m, __shfl_xor_sync(0xffffffffu, m, o));
            }
            m = fmaxf(m, 1e-20f);
            if (l == 0) {
                qsq[row] = s;
                qf_s[row] = 2.0f * m * (1.0f / 127.0f);   // fold the 2x here
            }
            uint32_t pk = pack4(v, 127.0f / m);
            uint32_t addr = sb + SM_QS
                          + (uint32_t)(row * 128 + (((l >> 2) ^ (row & 7)) << 4) + (l & 3) * 4);
            asm volatile("st.shared.b32 [%0], %1;" :: "r"(addr), "r"(pk) : "memory");
        }
    }
    // ---- whole-batch doc norms + dequant factors into smem ----
    {
        const float* s1 = g_Dsq + b * LD_;
        const float* s2 = g_Ddf + b * LD_;
        dsq_s[tid] = s1[tid];  dsq_s[tid + 256] = s1[tid + 256];
        ddf_s[tid] = s2[tid];  ddf_s[tid + 256] = s2[tid + 256];
    }

    // ---- ldmatrix lane addressing (16B granules, 8 per 128B row) ----
    const int jj = l >> 3;
    const int rr = l & 7;
    const int arow = wm * 32 + ((jj & 1) << 3) + rr;    // A: row group by jj&1
    const int achunk_off = jj >> 1;                     // A: chunk parity by jj>>1
    const int brow_base = wn * 32 + ((jj >> 1) << 3) + rr;  // B: row group by jj>>1
    const int bchunk_off = jj & 1;                      // B: chunk parity by jj&1

    const int tg = l >> 2;
    const int tc = l & 3;

    __syncthreads();   // Q smem fully written

    // ---- load ALL Q fragments once: a[mt][k][4] = 32 regs ----
    uint32_t a[2][4][4];
    #pragma unroll
    for (int mt = 0; mt < 2; mt++)
        #pragma unroll
        for (int k = 0; k < 4; k++) {
            uint32_t addr = sb + SM_QS + (uint32_t)((arow + mt * 16) * 128
                          + (((2 * k + achunk_off) ^ rr) << 4));
            ldmatrix_x4(a[mt][k][0], a[mt][k][1], a[mt][k][2], a[mt][k][3], addr);
        }

    // ---- per-thread q dequant factors (rows fixed for whole kernel) ----
    float qf[2][2];
    #pragma unroll
    for (int mt = 0; mt < 2; mt++) {
        qf[mt][0] = qf_s[wm * 32 + mt * 16 + tg];
        qf[mt][1] = qf_s[wm * 32 + mt * 16 + 8 + tg];
    }

    float rlo[2], rhi[2];
    #pragma unroll
    for (int mt = 0; mt < 2; mt++) { rlo[mt] = -3.402823e38f; rhi[mt] = -3.402823e38f; }

    #pragma unroll
    for (int c = 0; c < NCHUNK; c++) {
        if (c < NCHUNK - 1) cp_wait<1>(); else cp_wait<0>();
        __syncthreads();   // chunk c visible to all

        const uint32_t ds_cur_u = sb + SM_DS0 + (uint32_t)((c & 1) * 8192);

        int acc[2][4][4];
        #pragma unroll
        for (int mt = 0; mt < 2; mt++)
            #pragma unroll
            for (int nt = 0; nt < 4; nt++)
                #pragma unroll
                for (int e = 0; e < 4; e++) acc[mt][nt][e] = 0;

        // ---- B double buffer across the 4 k-steps ----
        uint32_t bf[2][4][2];
        #pragma unroll
        for (int p = 0; p < 2; p++) {   // prologue k=0
            uint32_t addr = ds_cur_u + (uint32_t)((brow_base + p * 16) * 128
                          + ((bchunk_off ^ rr) << 4));
            uint32_t r0, r1, r2, r3;
            ldmatrix_x4(r0, r1, r2, r3, addr);
            bf[0][p * 2 + 0][0] = r0; bf[0][p * 2 + 0][1] = r1;
            bf[0][p * 2 + 1][0] = r2; bf[0][p * 2 + 1][1] = r3;
        }

        #pragma unroll
        for (int k = 0; k < 4; k++) {
            const int cur = k & 1, nxt = cur ^ 1;
            if (k < 3) {
                #pragma unroll
                for (int p = 0; p < 2; p++) {
                    uint32_t addr = ds_cur_u + (uint32_t)((brow_base + p * 16) * 128
                                  + (((2 * (k + 1) + bchunk_off) ^ rr) << 4));
                    uint32_t r0, r1, r2, r3;
                    ldmatrix_x4(r0, r1, r2, r3, addr);
                    bf[nxt][p * 2 + 0][0] = r0; bf[nxt][p * 2 + 0][1] = r1;
                    bf[nxt][p * 2 + 1][0] = r2; bf[nxt][p * 2 + 1][1] = r3;
                }
            }
            #pragma unroll
            for (int mt = 0; mt < 2; mt++)
                #pragma unroll
                for (int nt = 0; nt < 4; nt++)
                    mma_16832_s8(acc[mt][nt][0], acc[mt][nt][1], acc[mt][nt][2], acc[mt][nt][3],
                                 a[mt][k][0], a[mt][k][1], a[mt][k][2], a[mt][k][3],
                                 bf[cur][nt][0], bf[cur][nt][1]);
        }

        // ---- refill this buffer with chunk c+2 ASAP ----
        if (c < NCHUNK - 2) {
            __syncthreads();
            const char* src_base = reinterpret_cast<const char*>(Dq_b + (size_t)(c + 2) * TN * DIM);
            uint32_t dst_base = sb + SM_DS0 + (uint32_t)((c & 1) * 8192);
            #pragma unroll
            for (int j = 0; j < 2; j++) {
                int idx = tid + 256 * j;
                int r = idx >> 3, cc = idx & 7;
                cp_async16(dst_base + (uint32_t)(r * 128 + (((cc ^ (r & 7)) << 4))),
                           src_base + r * 128 + cc * 16);
            }
            cp_commit();
        }

        // ---- epilogue: dequant, neg_dist = (2q).d - d^2, running max ----
        #pragma unroll
        for (int nt = 0; nt < 4; nt++) {
            int n_off = c * TN + wn * 32 + nt * 8 + tc * 2;
            float2 ds2 = *reinterpret_cast<float2*>(&dsq_s[n_off]);
            float2 df2 = *reinterpret_cast<float2*>(&ddf_s[n_off]);
            #pragma unroll
            for (int mt = 0; mt < 2; mt++) {
                float a0 = __int2float_rn(acc[mt][nt][0]);
                float a1 = __int2float_rn(acc[mt][nt][1]);
                float a2 = __int2float_rn(acc[mt][nt][2]);
                float a3 = __int2float_rn(acc[mt][nt][3]);
                float v00 = fmaf(a0, qf[mt][0] * df2.x, -ds2.x);
                float v01 = fmaf(a1, qf[mt][0] * df2.y, -ds2.y);
                float v10 = fmaf(a2, qf[mt][1] * df2.x, -ds2.x);
                float v11 = fmaf(a3, qf[mt][1] * df2.y, -ds2.y);
                rlo[mt] = fmaxf(rlo[mt], fmaxf(v00, v01));
                rhi[mt] = fmaxf(rhi[mt], fmaxf(v10, v11));
            }
        }
    }

    // ---- cross-lane max (cols in lane bits 0..1) ----
    #pragma unroll
    for (int mt = 0; mt < 2; mt++) {
        rlo[mt] = fmaxf(rlo[mt], __shfl_xor_sync(0xffffffffu, rlo[mt], 1));
        rlo[mt] = fmaxf(rlo[mt], __shfl_xor_sync(0xffffffffu, rlo[mt], 2));
        rhi[mt] = fmaxf(rhi[mt], __shfl_xor_sync(0xffffffffu, rhi[mt], 1));
        rhi[mt] = fmaxf(rhi[mt], __shfl_xor_sync(0xffffffffu, rhi[mt], 2));
    }
    if (tc == 0) {
        #pragma unroll
        for (int mt = 0; mt < 2; mt++) {
            maxbuf[(wm * 32 + mt * 16 + tg) * 2 + wn]     = rlo[mt];
            maxbuf[(wm * 32 + mt * 16 + 8 + tg) * 2 + wn] = rhi[mt];
        }
    }
    __syncthreads();

    // ---- row max across 2 warp-cols, subtract ||q||^2, block sum ----
    float val = 0.0f;
    if (tid < TM) {
        float2 m2 = *reinterpret_cast<float2*>(&maxbuf[tid * 2]);
        val = fmaxf(m2.x, m2.y) - qsq[tid];
    }
    #pragma unroll
    for (int o = 16; o > 0; o >>= 1) val += __shfl_xor_sync(0xffffffffu, val, o);
    if (l == 0) red[w] = val;
    __syncthreads();
    if (tid == 0) {
        float s = 0.0f;
        #pragma unroll
        for (int i = 0; i < 8; i++) s += red[i];
        atomicAdd(&out[b], s);
    }
}

extern "C" void kernel_launch(void* const* d_in, const int* in_sizes, int n_in,
                              void* d_out, int out_size) {
    const float* Qg = (const float*)d_in[0];
    const float* Dg = (const float*)d_in[1];
    float* out = (float*)d_out;

    static int attr_set = 0;
    if (!attr_set) {
        cudaFuncSetAttribute(colbert_mma_kernel,
                             cudaFuncAttributeMaxDynamicSharedMemorySize, SMEM_TOTAL);
        attr_set = 1;
    }

    convert_d_kernel<<<(B_ * LD_) / 128, NTHREADS>>>(Dg, out);
    colbert_mma_kernel<<<B_ * (LQ_ / TM), NTHREADS, SMEM_TOTAL>>>(Qg, out);
}

// round 15
// speedup vs baseline: 1.1080x; 1.0154x over previous
#include <cuda_runtime.h>
#include <cstdint>

#define B_    128
#define LQ_   512
#define LD_   512
#define DIM   128
#define TM    128            // q rows per CTA
#define TN    64             // doc rows per chunk
#define NCHUNK (LD_ / TN)    // 8
#define NTHREADS 256

// ---- global scratch: int8-quantized D + exact fp32 row norms + dequant scales ----
__device__ int8_t g_Dq[B_ * LD_ * DIM];           // 8 MB
__device__ float  g_Dsq[B_ * LD_];                // 256 KB
__device__ float  g_Ddf[B_ * LD_];                // dequant factor maxabs/127

// ---- kernel-2 smem layout (bytes) ----
#define SM_QS    0                      // 128x128 int8 swizzled = 16384
#define SM_DS0   16384                  // 4 ring buffers x 8192 = 32768
#define SM_DSQ   49152                  // 512 floats = 2048
#define SM_DDF   51200                  // 512 floats = 2048
#define SM_QSQ   53248                  // 128 floats = 512
#define SM_QF    53760                  // 128 floats = 512
#define SM_MAX   54272                  // 128*2 floats = 1024
#define SM_RED   55296                  // 8 floats
#define SMEM_TOTAL (SM_RED + 64)        // 55360

__device__ __forceinline__ uint32_t smem_u32(const void* p) {
    uint32_t a;
    asm("{ .reg .u64 t; cvta.to.shared.u64 t, %1; cvt.u32.u64 %0, t; }" : "=r"(a) : "l"(p));
    return a;
}

__device__ __forceinline__ void ldmatrix_x4(uint32_t& r0, uint32_t& r1,
                                            uint32_t& r2, uint32_t& r3, uint32_t addr) {
    asm volatile("ldmatrix.sync.aligned.m8n8.x4.shared.b16 {%0,%1,%2,%3}, [%4];"
                 : "=r"(r0), "=r"(r1), "=r"(r2), "=r"(r3) : "r"(addr));
}

// s8 x s8 -> s32, K=32 per instruction (exact integer accumulate)
__device__ __forceinline__ void mma_16832_s8(int& c0, int& c1, int& c2, int& c3,
                                             uint32_t a0, uint32_t a1, uint32_t a2, uint32_t a3,
                                             uint32_t b0, uint32_t b1) {
    asm volatile("mma.sync.aligned.m16n8k32.row.col.s32.s8.s8.s32 "
                 "{%0,%1,%2,%3}, {%4,%5,%6,%7}, {%8,%9}, {%0,%1,%2,%3};"
                 : "+r"(c0), "+r"(c1), "+r"(c2), "+r"(c3)
                 : "r"(a0), "r"(a1), "r"(a2), "r"(a3), "r"(b0), "r"(b1));
}

__device__ __forceinline__ void cp_async16(uint32_t dst, const void* src) {
    asm volatile("cp.async.cg.shared.global [%0], [%1], 16;" :: "r"(dst), "l"(src));
}
__device__ __forceinline__ void cp_commit() {
    asm volatile("cp.async.commit_group;" ::: "memory");
}
template <int N>
__device__ __forceinline__ void cp_wait() {
    asm volatile("cp.async.wait_group %0;" :: "n"(N) : "memory");
}

__device__ __forceinline__ uint32_t pack4(float4 v, float S) {
    int a = __float2int_rn(v.x * S), b = __float2int_rn(v.y * S);
    int c = __float2int_rn(v.z * S), d = __float2int_rn(v.w * S);
    return (uint32_t)(a & 0xff) | ((uint32_t)(b & 0xff) << 8)
         | ((uint32_t)(c & 0xff) << 16) | ((uint32_t)(d & 0xff) << 24);
}

// ============ kernel 1: D fp32 -> int8 (per-row scale) + norms (+ zero out) ====
__global__ void __launch_bounds__(NTHREADS)
convert_d_kernel(const float* __restrict__ Dg, float* __restrict__ out) {
    const int tid = threadIdx.x;
    const int w = tid >> 5, l = tid & 31;
    const int rsub = l >> 3;
    const int piece = l & 7;

    if (blockIdx.x == 0 && tid < B_) out[tid] = 0.0f;

    #pragma unroll
    for (int pass = 0; pass < 4; pass++) {
        int row = blockIdx.x * 128 + w * 16 + pass * 4 + rsub;
        const float4* src = reinterpret_cast<const float4*>(Dg + (size_t)row * DIM);
        float4 v[4];
        #pragma unroll
        for (int i = 0; i < 4; i++) v[i] = src[piece + 8 * i];

        float s = 0.0f, m = 0.0f;
        #pragma unroll
        for (int i = 0; i < 4; i++) {
            s += v[i].x * v[i].x + v[i].y * v[i].y + v[i].z * v[i].z + v[i].w * v[i].w;
            m = fmaxf(m, fmaxf(fmaxf(fabsf(v[i].x), fabsf(v[i].y)),
                               fmaxf(fabsf(v[i].z), fabsf(v[i].w))));
        }
        #pragma unroll
        for (int o = 4; o > 0; o >>= 1) {
            s += __shfl_xor_sync(0xffffffffu, s, o);
            m = fmaxf(m, __shfl_xor_sync(0xffffffffu, m, o));
        }
        m = fmaxf(m, 1e-20f);
        if (piece == 0) {
            g_Dsq[row] = s;
            g_Ddf[row] = m * (1.0f / 127.0f);
        }
        float S = 127.0f / m;
        uint32_t* qrow = reinterpret_cast<uint32_t*>(g_Dq + (size_t)row * DIM);
        #pragma unroll
        for (int i = 0; i < 4; i++) qrow[piece + 8 * i] = pack4(v[i], S);
    }
}

// ============ kernel 2: int8 IMMA GEMM + fused dequant/max/sum epilogue =========
__global__ void __launch_bounds__(NTHREADS, 3)
colbert_mma_kernel(const float* __restrict__ Qg, float* __restrict__ out) {
    extern __shared__ char smem[];
    const uint32_t sb = smem_u32(smem);
    float* dsq_s  = reinterpret_cast<float*>(smem + SM_DSQ);
    float* ddf_s  = reinterpret_cast<float*>(smem + SM_DDF);
    float* qsq    = reinterpret_cast<float*>(smem + SM_QSQ);
    float* qf_s   = reinterpret_cast<float*>(smem + SM_QF);
    float* maxbuf = reinterpret_cast<float*>(smem + SM_MAX);
    float* red    = reinterpret_cast<float*>(smem + SM_RED);

    const int tid = threadIdx.x;
    const int w = tid >> 5, l = tid & 31;
    const int wm = w >> 1;               // 0..3 : 32-row M block
    const int wn = w & 1;                // 0..1 : 32-col N block

    const int b  = blockIdx.x >> 2;
    const int qt = blockIdx.x & 3;
    const float* Qb = Qg + ((size_t)(b * LQ_ + qt * TM)) * DIM;
    const int8_t* Dq_b = g_Dq + (size_t)b * LD_ * DIM;

    // ---- issue cp.async for chunks 0,1,2 into ring bufs 0,1,2 ----
    {
        #pragma unroll
        for (int cbuf = 0; cbuf < 3; cbuf++) {
            const char* src_base = reinterpret_cast<const char*>(Dq_b + (size_t)cbuf * TN * DIM);
            uint32_t dst_base = sb + SM_DS0 + (uint32_t)(cbuf * 8192);
            #pragma unroll
            for (int j = 0; j < 2; j++) {
                int idx = tid + 256 * j;
                int r = idx >> 3, cc = idx & 7;
                cp_async16(dst_base + (uint32_t)(r * 128 + (((cc ^ (r & 7)) << 4))),
                           src_base + r * 128 + cc * 16);
            }
            cp_commit();
        }
    }

    // ---- convert Q tile fp32 -> int8 (per-row scale) swizzled smem + qsq/qf ----
    {
        #pragma unroll
        for (int j = 0; j < TM / 8; j++) {
            int row = j * 8 + w;
            float4 v = reinterpret_cast<const float4*>(Qb)[row * 32 + l];
            float s = v.x * v.x + v.y * v.y + v.z * v.z + v.w * v.w;
            float m = fmaxf(fmaxf(fabsf(v.x), fabsf(v.y)), fmaxf(fabsf(v.z), fabsf(v.w)));
            #pragma unroll
            for (int o = 16; o > 0; o >>= 1) {
                s += __shfl_xor_sync(0xffffffffu, s, o);
                m = fmaxf(m, __shfl_xor_sync(0xffffffffu, m, o));
            }
            m = fmaxf(m, 1e-20f);
            if (l == 0) {
                qsq[row] = s;
                qf_s[row] = 2.0f * m * (1.0f / 127.0f);   // fold the 2x here
            }
            uint32_t pk = pack4(v, 127.0f / m);
            uint32_t addr = sb + SM_QS
                          + (uint32_t)(row * 128 + (((l >> 2) ^ (row & 7)) << 4) + (l & 3) * 4);
            asm volatile("st.shared.b32 [%0], %1;" :: "r"(addr), "r"(pk) : "memory");
        }
    }
    // ---- whole-batch doc norms + dequant factors into smem ----
    {
        const float* s1 = g_Dsq + b * LD_;
        const float* s2 = g_Ddf + b * LD_;
        dsq_s[tid] = s1[tid];  dsq_s[tid + 256] = s1[tid + 256];
        ddf_s[tid] = s2[tid];  ddf_s[tid + 256] = s2[tid + 256];
    }

    // ---- ldmatrix lane addressing (16B granules, 8 per 128B row) ----
    const int jj = l >> 3;
    const int rr = l & 7;
    const int arow = wm * 32 + ((jj & 1) << 3) + rr;
    const int achunk_off = jj >> 1;
    const int brow_base = wn * 32 + ((jj >> 1) << 3) + rr;
    const int bchunk_off = jj & 1;

    const int tg = l >> 2;
    const int tc = l & 3;

    __syncthreads();   // Q smem + qf fully written

    // ---- per-thread q dequant factors (rows fixed for whole kernel) ----
    float qf[2][2];
    #pragma unroll
    for (int mt = 0; mt < 2; mt++) {
        qf[mt][0] = qf_s[wm * 32 + mt * 16 + tg];
        qf[mt][1] = qf_s[wm * 32 + mt * 16 + 8 + tg];
    }

    float rlo[2], rhi[2];
    #pragma unroll
    for (int mt = 0; mt < 2; mt++) { rlo[mt] = -3.402823e38f; rhi[mt] = -3.402823e38f; }

    #pragma unroll
    for (int c = 0; c < NCHUNK; c++) {
        cp_wait<2>();      // chunk c landed (pending: c+1, c+2)
        __syncthreads();   // all warps past chunk c-1 (ring buffer (c-1)&3 free)

        // ---- issue refill for chunk c+3 into buf (c+3)&3 = (c-1)&3 ----
        if (c + 3 < NCHUNK) {
            const char* src_base = reinterpret_cast<const char*>(Dq_b + (size_t)(c + 3) * TN * DIM);
            uint32_t dst_base = sb + SM_DS0 + (uint32_t)(((c + 3) & 3) * 8192);
            #pragma unroll
            for (int j = 0; j < 2; j++) {
                int idx = tid + 256 * j;
                int r = idx >> 3, cc = idx & 7;
                cp_async16(dst_base + (uint32_t)(r * 128 + (((cc ^ (r & 7)) << 4))),
                           src_base + r * 128 + cc * 16);
            }
        }
        cp_commit();       // commit unconditionally to keep group counting static

        const uint32_t ds_cur_u = sb + SM_DS0 + (uint32_t)((c & 3) * 8192);

        int acc[2][4][4];
        #pragma unroll
        for (int mt = 0; mt < 2; mt++)
            #pragma unroll
            for (int nt = 0; nt < 4; nt++)
                #pragma unroll
                for (int e = 0; e < 4; e++) acc[mt][nt][e] = 0;

        #pragma unroll
        for (int k = 0; k < 4; k++) {
            uint32_t a[2][4];
            #pragma unroll
            for (int mt = 0; mt < 2; mt++) {
                uint32_t addr = sb + SM_QS + (uint32_t)((arow + mt * 16) * 128
                              + (((2 * k + achunk_off) ^ rr) << 4));
                ldmatrix_x4(a[mt][0], a[mt][1], a[mt][2], a[mt][3], addr);
            }
            uint32_t bf[4][2];
            #pragma unroll
            for (int p = 0; p < 2; p++) {
                uint32_t addr = ds_cur_u + (uint32_t)((brow_base + p * 16) * 128
                              + (((2 * k + bchunk_off) ^ rr) << 4));
                uint32_t r0, r1, r2, r3;
                ldmatrix_x4(r0, r1, r2, r3, addr);
                bf[p * 2 + 0][0] = r0; bf[p * 2 + 0][1] = r1;
                bf[p * 2 + 1][0] = r2; bf[p * 2 + 1][1] = r3;
            }
            #pragma unroll
            for (int mt = 0; mt < 2; mt++)
                #pragma unroll
                for (int nt = 0; nt < 4; nt++)
                    mma_16832_s8(acc[mt][nt][0], acc[mt][nt][1], acc[mt][nt][2], acc[mt][nt][3],
                                 a[mt][0], a[mt][1], a[mt][2], a[mt][3],
                                 bf[nt][0], bf[nt][1]);
        }

        // ---- epilogue: dequant, neg_dist = (2q).d - d^2, running max ----
        #pragma unroll
        for (int nt = 0; nt < 4; nt++) {
            int n_off = c * TN + wn * 32 + nt * 8 + tc * 2;
            float2 ds2 = *reinterpret_cast<float2*>(&dsq_s[n_off]);
            float2 df2 = *reinterpret_cast<float2*>(&ddf_s[n_off]);
            #pragma unroll
            for (int mt = 0; mt < 2; mt++) {
                float a0 = __int2float_rn(acc[mt][nt][0]);
                float a1 = __int2float_rn(acc[mt][nt][1]);
                float a2 = __int2float_rn(acc[mt][nt][2]);
                float a3 = __int2float_rn(acc[mt][nt][3]);
                float v00 = fmaf(a0, qf[mt][0] * df2.x, -ds2.x);
                float v01 = fmaf(a1, qf[mt][0] * df2.y, -ds2.y);
                float v10 = fmaf(a2, qf[mt][1] * df2.x, -ds2.x);
                float v11 = fmaf(a3, qf[mt][1] * df2.y, -ds2.y);
                rlo[mt] = fmaxf(rlo[mt], fmaxf(v00, v01));
                rhi[mt] = fmaxf(rhi[mt], fmaxf(v10, v11));
            }
        }
    }

    // ---- cross-lane max (cols in lane bits 0..1) ----
    #pragma unroll
    for (int mt = 0; mt < 2; mt++) {
        rlo[mt] = fmaxf(rlo[mt], __shfl_xor_sync(0xffffffffu, rlo[mt], 1));
        rlo[mt] = fmaxf(rlo[mt], __shfl_xor_sync(0xffffffffu, rlo[mt], 2));
        rhi[mt] = fmaxf(rhi[mt], __shfl_xor_sync(0xffffffffu, rhi[mt], 1));
        rhi[mt] = fmaxf(rhi[mt], __shfl_xor_sync(0xffffffffu, rhi[mt], 2));
    }
    if (tc == 0) {
        #pragma unroll
        for (int mt = 0; mt < 2; mt++) {
            maxbuf[(wm * 32 + mt * 16 + tg) * 2 + wn]     = rlo[mt];
            maxbuf[(wm * 32 + mt * 16 + 8 + tg) * 2 + wn] = rhi[mt];
        }
    }
    __syncthreads();

    // ---- row max across 2 warp-cols, subtract ||q||^2, block sum ----
    float val = 0.0f;
    if (tid < TM) {
        float2 m2 = *reinterpret_cast<float2*>(&maxbuf[tid * 2]);
        val = fmaxf(m2.x, m2.y) - qsq[tid];
    }
    #pragma unroll
    for (int o = 16; o > 0; o >>= 1) val += __shfl_xor_sync(0xffffffffu, val, o);
    if (l == 0) red[w] = val;
    __syncthreads();
    if (tid == 0) {
        float s = 0.0f;
        #pragma unroll
        for (int i = 0; i < 8; i++) s += red[i];
        atomicAdd(&out[b], s);
    }
}

extern "C" void kernel_launch(void* const* d_in, const int* in_sizes, int n_in,
                              void* d_out, int out_size) {
    const float* Qg = (const float*)d_in[0];
    const float* Dg = (const float*)d_in[1];
    float* out = (float*)d_out;

    static int attr_set = 0;
    if (!attr_set) {
        cudaFuncSetAttribute(colbert_mma_kernel,
                             cudaFuncAttributeMaxDynamicSharedMemorySize, SMEM_TOTAL);
        attr_set = 1;
    }

    convert_d_kernel<<<(B_ * LD_) / 128, NTHREADS>>>(Dg, out);
    colbert_mma_kernel<<<B_ * (LQ_ / TM), NTHREADS, SMEM_TOTAL>>>(Qg, out);
}

// round 16
// speedup vs baseline: 1.2523x; 1.1303x over previous
#include <cuda_runtime.h>
#include <cstdint>

#define B_    128
#define LQ_   512
#define LD_   512
#define DIM   128
#define TM    128            // q rows per CTA
#define TN    64             // doc rows per chunk
#define NCHUNK (LD_ / TN)    // 8
#define NTHREADS 256

// ---- global scratch: int8-quantized Q & D + exact fp32 row norms + dequant scales ----
__device__ int8_t g_Dq[B_ * LD_ * DIM];           // 8 MB
__device__ float  g_Dsq[B_ * LD_];
__device__ float  g_Ddf[B_ * LD_];                // maxabs/127
__device__ int8_t g_Qq[B_ * LQ_ * DIM];           // 8 MB
__device__ float  g_Qsq[B_ * LQ_];
__device__ float  g_Qf[B_ * LQ_];                 // 2*maxabs/127 (2x folded)

// ---- kernel-2 smem layout (bytes) ----
#define SM_QS    0                      // 128x128 int8 swizzled = 16384
#define SM_DS0   16384                  // 4 ring buffers x 8192 = 32768
#define SM_DSQ   49152                  // 512 floats = 2048
#define SM_DDF   51200                  // 512 floats = 2048
#define SM_QSQ   53248                  // 128 floats = 512
#define SM_QF    53760                  // 128 floats = 512
#define SM_MAX   54272                  // 128*2 floats = 1024
#define SM_RED   55296                  // 8 floats
#define SMEM_TOTAL (SM_RED + 64)        // 55360

__device__ __forceinline__ uint32_t smem_u32(const void* p) {
    uint32_t a;
    asm("{ .reg .u64 t; cvta.to.shared.u64 t, %1; cvt.u32.u64 %0, t; }" : "=r"(a) : "l"(p));
    return a;
}

__device__ __forceinline__ void ldmatrix_x4(uint32_t& r0, uint32_t& r1,
                                            uint32_t& r2, uint32_t& r3, uint32_t addr) {
    asm volatile("ldmatrix.sync.aligned.m8n8.x4.shared.b16 {%0,%1,%2,%3}, [%4];"
                 : "=r"(r0), "=r"(r1), "=r"(r2), "=r"(r3) : "r"(addr));
}

__device__ __forceinline__ void mma_16832_s8(int& c0, int& c1, int& c2, int& c3,
                                             uint32_t a0, uint32_t a1, uint32_t a2, uint32_t a3,
                                             uint32_t b0, uint32_t b1) {
    asm volatile("mma.sync.aligned.m16n8k32.row.col.s32.s8.s8.s32 "
                 "{%0,%1,%2,%3}, {%4,%5,%6,%7}, {%8,%9}, {%0,%1,%2,%3};"
                 : "+r"(c0), "+r"(c1), "+r"(c2), "+r"(c3)
                 : "r"(a0), "r"(a1), "r"(a2), "r"(a3), "r"(b0), "r"(b1));
}

__device__ __forceinline__ void cp_async16(uint32_t dst, const void* src) {
    asm volatile("cp.async.cg.shared.global [%0], [%1], 16;" :: "r"(dst), "l"(src));
}
__device__ __forceinline__ void cp_commit() {
    asm volatile("cp.async.commit_group;" ::: "memory");
}
template <int N>
__device__ __forceinline__ void cp_wait() {
    asm volatile("cp.async.wait_group %0;" :: "n"(N) : "memory");
}

__device__ __forceinline__ uint32_t pack4(float4 v, float S) {
    int a = __float2int_rn(v.x * S), b = __float2int_rn(v.y * S);
    int c = __float2int_rn(v.z * S), d = __float2int_rn(v.w * S);
    return (uint32_t)(a & 0xff) | ((uint32_t)(b & 0xff) << 8)
         | ((uint32_t)(c & 0xff) << 16) | ((uint32_t)(d & 0xff) << 24);
}

// ========= kernel 1: Q and D fp32 -> int8 (per-row scale) + norms (+ zero out) =====
// grid 1024: blocks [0,512) handle D rows, [512,1024) handle Q rows.
__global__ void __launch_bounds__(NTHREADS)
convert_qd_kernel(const float* __restrict__ Qg, const float* __restrict__ Dg,
                  float* __restrict__ out) {
    const int tid = threadIdx.x;
    const int w = tid >> 5, l = tid & 31;
    const int rsub = l >> 3;
    const int piece = l & 7;

    if (blockIdx.x == 0 && tid < B_) out[tid] = 0.0f;

    const bool isQ = blockIdx.x >= 512;
    const int blk = isQ ? (blockIdx.x - 512) : blockIdx.x;
    const float* src_g = isQ ? Qg : Dg;
    int8_t* dst_q = isQ ? g_Qq : g_Dq;
    float* dst_sq = isQ ? g_Qsq : g_Dsq;
    float* dst_f  = isQ ? g_Qf : g_Ddf;
    const float fscale = isQ ? (2.0f / 127.0f) : (1.0f / 127.0f);

    #pragma unroll
    for (int pass = 0; pass < 4; pass++) {
        int row = blk * 128 + w * 16 + pass * 4 + rsub;
        const float4* src = reinterpret_cast<const float4*>(src_g + (size_t)row * DIM);
        float4 v[4];
        #pragma unroll
        for (int i = 0; i < 4; i++) v[i] = src[piece + 8 * i];

        float s = 0.0f, m = 0.0f;
        #pragma unroll
        for (int i = 0; i < 4; i++) {
            s += v[i].x * v[i].x + v[i].y * v[i].y + v[i].z * v[i].z + v[i].w * v[i].w;
            m = fmaxf(m, fmaxf(fmaxf(fabsf(v[i].x), fabsf(v[i].y)),
                               fmaxf(fabsf(v[i].z), fabsf(v[i].w))));
        }
        #pragma unroll
        for (int o = 4; o > 0; o >>= 1) {
            s += __shfl_xor_sync(0xffffffffu, s, o);
            m = fmaxf(m, __shfl_xor_sync(0xffffffffu, m, o));
        }
        m = fmaxf(m, 1e-20f);
        if (piece == 0) {
            dst_sq[row] = s;
            dst_f[row]  = m * fscale;
        }
        float S = 127.0f / m;
        uint32_t* qrow = reinterpret_cast<uint32_t*>(dst_q + (size_t)row * DIM);
        #pragma unroll
        for (int i = 0; i < 4; i++) qrow[piece + 8 * i] = pack4(v[i], S);
    }
}

// ============ kernel 2: int8 IMMA GEMM + fused dequant/max/sum epilogue =========
__global__ void __launch_bounds__(NTHREADS, 3)
colbert_mma_kernel(float* __restrict__ out) {
    extern __shared__ char smem[];
    const uint32_t sb = smem_u32(smem);
    float* dsq_s  = reinterpret_cast<float*>(smem + SM_DSQ);
    float* ddf_s  = reinterpret_cast<float*>(smem + SM_DDF);
    float* qsq    = reinterpret_cast<float*>(smem + SM_QSQ);
    float* qf_s   = reinterpret_cast<float*>(smem + SM_QF);
    float* maxbuf = reinterpret_cast<float*>(smem + SM_MAX);
    float* red    = reinterpret_cast<float*>(smem + SM_RED);

    const int tid = threadIdx.x;
    const int w = tid >> 5, l = tid & 31;
    const int wm = w >> 1;               // 0..3 : 32-row M block
    const int wn = w & 1;                // 0..1 : 32-col N block

    const int b  = blockIdx.x >> 2;
    const int qt = blockIdx.x & 3;
    const int qrow0 = b * LQ_ + qt * TM;
    const int8_t* Qq_b = g_Qq + (size_t)qrow0 * DIM;
    const int8_t* Dq_b = g_Dq + (size_t)b * LD_ * DIM;

    // ---- group 0: Q tile (1024 granules) + D chunk 0 (512 granules) ----
    {
        #pragma unroll
        for (int j = 0; j < 4; j++) {
            int idx = tid + 256 * j;
            int r = idx >> 3, cc = idx & 7;
            cp_async16(sb + SM_QS + (uint32_t)(r * 128 + (((cc ^ (r & 7)) << 4))),
                       reinterpret_cast<const char*>(Qq_b) + r * 128 + cc * 16);
        }
        #pragma unroll
        for (int j = 0; j < 2; j++) {
            int idx = tid + 256 * j;
            int r = idx >> 3, cc = idx & 7;
            cp_async16(sb + SM_DS0 + (uint32_t)(r * 128 + (((cc ^ (r & 7)) << 4))),
                       reinterpret_cast<const char*>(Dq_b) + r * 128 + cc * 16);
        }
        cp_commit();
        // groups 1,2: D chunks 1,2
        #pragma unroll
        for (int cbuf = 1; cbuf < 3; cbuf++) {
            const char* src_base = reinterpret_cast<const char*>(Dq_b + (size_t)cbuf * TN * DIM);
            uint32_t dst_base = sb + SM_DS0 + (uint32_t)(cbuf * 8192);
            #pragma unroll
            for (int j = 0; j < 2; j++) {
                int idx = tid + 256 * j;
                int r = idx >> 3, cc = idx & 7;
                cp_async16(dst_base + (uint32_t)(r * 128 + (((cc ^ (r & 7)) << 4))),
                           src_base + r * 128 + cc * 16);
            }
            cp_commit();
        }
    }

    // ---- scalar metadata into smem: qsq/qf (128 ea) + dsq/ddf (512 ea) ----
    if (tid < 128) {
        qsq[tid]  = g_Qsq[qrow0 + tid];
        qf_s[tid] = g_Qf[qrow0 + tid];
    }
    {
        const float* s1 = g_Dsq + b * LD_;
        const float* s2 = g_Ddf + b * LD_;
        dsq_s[tid] = s1[tid];  dsq_s[tid + 256] = s1[tid + 256];
        ddf_s[tid] = s2[tid];  ddf_s[tid + 256] = s2[tid + 256];
    }

    // ---- ldmatrix lane addressing (16B granules, 8 per 128B row) ----
    const int jj = l >> 3;
    const int rr = l & 7;
    const int arow = wm * 32 + ((jj & 1) << 3) + rr;
    const int achunk_off = jj >> 1;
    const int brow_base = wn * 32 + ((jj >> 1) << 3) + rr;
    const int bchunk_off = jj & 1;

    const int tg = l >> 2;
    const int tc = l & 3;

    __syncthreads();   // metadata smem visible

    // ---- per-thread q dequant factors (rows fixed for whole kernel) ----
    float qf[2][2];
    #pragma unroll
    for (int mt = 0; mt < 2; mt++) {
        qf[mt][0] = qf_s[wm * 32 + mt * 16 + tg];
        qf[mt][1] = qf_s[wm * 32 + mt * 16 + 8 + tg];
    }

    float rlo[2], rhi[2];
    #pragma unroll
    for (int mt = 0; mt < 2; mt++) { rlo[mt] = -3.402823e38f; rhi[mt] = -3.402823e38f; }

    #pragma unroll
    for (int c = 0; c < NCHUNK; c++) {
        cp_wait<2>();      // group c landed (c=0: Q + D0)
        __syncthreads();   // all warps past chunk c-1 (ring buffer (c-1)&3 free)

        // ---- issue refill for chunk c+3 into buf (c+3)&3 = (c-1)&3 ----
        if (c + 3 < NCHUNK) {
            const char* src_base = reinterpret_cast<const char*>(Dq_b + (size_t)(c + 3) * TN * DIM);
            uint32_t dst_base = sb + SM_DS0 + (uint32_t)(((c + 3) & 3) * 8192);
            #pragma unroll
            for (int j = 0; j < 2; j++) {
                int idx = tid + 256 * j;
                int r = idx >> 3, cc = idx & 7;
                cp_async16(dst_base + (uint32_t)(r * 128 + (((cc ^ (r & 7)) << 4))),
                           src_base + r * 128 + cc * 16);
            }
        }
        cp_commit();       // commit unconditionally to keep group counting static

        const uint32_t ds_cur_u = sb + SM_DS0 + (uint32_t)((c & 3) * 8192);

        int acc[2][4][4];
        #pragma unroll
        for (int mt = 0; mt < 2; mt++)
            #pragma unroll
            for (int nt = 0; nt < 4; nt++)
                #pragma unroll
                for (int e = 0; e < 4; e++) acc[mt][nt][e] = 0;

        #pragma unroll
        for (int k = 0; k < 4; k++) {
            uint32_t a[2][4];
            #pragma unroll
            for (int mt = 0; mt < 2; mt++) {
                uint32_t addr = sb + SM_QS + (uint32_t)((arow + mt * 16) * 128
                              + (((2 * k + achunk_off) ^ rr) << 4));
                ldmatrix_x4(a[mt][0], a[mt][1], a[mt][2], a[mt][3], addr);
            }
            uint32_t bf[4][2];
            #pragma unroll
            for (int p = 0; p < 2; p++) {
                uint32_t addr = ds_cur_u + (uint32_t)((brow_base + p * 16) * 128
                              + (((2 * k + bchunk_off) ^ rr) << 4));
                uint32_t r0, r1, r2, r3;
                ldmatrix_x4(r0, r1, r2, r3, addr);
                bf[p * 2 + 0][0] = r0; bf[p * 2 + 0][1] = r1;
                bf[p * 2 + 1][0] = r2; bf[p * 2 + 1][1] = r3;
            }
            #pragma unroll
            for (int mt = 0; mt < 2; mt++)
                #pragma unroll
                for (int nt = 0; nt < 4; nt++)
                    mma_16832_s8(acc[mt][nt][0], acc[mt][nt][1], acc[mt][nt][2], acc[mt][nt][3],
                                 a[mt][0], a[mt][1], a[mt][2], a[mt][3],
                                 bf[nt][0], bf[nt][1]);
        }

        // ---- epilogue: dequant, neg_dist = (2q).d - d^2, running max ----
        #pragma unroll
        for (int nt = 0; nt < 4; nt++) {
            int n_off = c * TN + wn * 32 + nt * 8 + tc * 2;
            float2 ds2 = *reinterpret_cast<float2*>(&dsq_s[n_off]);
            float2 df2 = *reinterpret_cast<float2*>(&ddf_s[n_off]);
            #pragma unroll
            for (int mt = 0; mt < 2; mt++) {
                float a0 = __int2float_rn(acc[mt][nt][0]);
                float a1 = __int2float_rn(acc[mt][nt][1]);
                float a2 = __int2float_rn(acc[mt][nt][2]);
                float a3 = __int2float_rn(acc[mt][nt][3]);
                float v00 = fmaf(a0, qf[mt][0] * df2.x, -ds2.x);
                float v01 = fmaf(a1, qf[mt][0] * df2.y, -ds2.y);
                float v10 = fmaf(a2, qf[mt][1] * df2.x, -ds2.x);
                float v11 = fmaf(a3, qf[mt][1] * df2.y, -ds2.y);
                rlo[mt] = fmaxf(rlo[mt], fmaxf(v00, v01));
                rhi[mt] = fmaxf(rhi[mt], fmaxf(v10, v11));
            }
        }
    }

    // ---- cross-lane max (cols in lane bits 0..1) ----
    #pragma unroll
    for (int mt = 0; mt < 2; mt++) {
        rlo[mt] = fmaxf(rlo[mt], __shfl_xor_sync(0xffffffffu, rlo[mt], 1));
        rlo[mt] = fmaxf(rlo[mt], __shfl_xor_sync(0xffffffffu, rlo[mt], 2));
        rhi[mt] = fmaxf(rhi[mt], __shfl_xor_sync(0xffffffffu, rhi[mt], 1));
        rhi[mt] = fmaxf(rhi[mt], __shfl_xor_sync(0xffffffffu, rhi[mt], 2));
    }
    if (tc == 0) {
        #pragma unroll
        for (int mt = 0; mt < 2; mt++) {
            maxbuf[(wm * 32 + mt * 16 + tg) * 2 + wn]     = rlo[mt];
            maxbuf[(wm * 32 + mt * 16 + 8 + tg) * 2 + wn] = rhi[mt];
        }
    }
    __syncthreads();

    // ---- row max across 2 warp-cols, subtract ||q||^2, block sum ----
    float val = 0.0f;
    if (tid < TM) {
        float2 m2 = *reinterpret_cast<float2*>(&maxbuf[tid * 2]);
        val = fmaxf(m2.x, m2.y) - qsq[tid];
    }
    #pragma unroll
    for (int o = 16; o > 0; o >>= 1) val += __shfl_xor_sync(0xffffffffu, val, o);
    if (l == 0) red[w] = val;
    __syncthreads();
    if (tid == 0) {
        float s = 0.0f;
        #pragma unroll
        for (int i = 0; i < 8; i++) s += red[i];
        atomicAdd(&out[b], s);
    }
}

extern "C" void kernel_launch(void* const* d_in, const int* in_sizes, int n_in,
                              void* d_out, int out_size) {
    const float* Qg = (const float*)d_in[0];
    const float* Dg = (const float*)d_in[1];
    float* out = (float*)d_out;

    static int attr_set = 0;
    if (!attr_set) {
        cudaFuncSetAttribute(colbert_mma_kernel,
                             cudaFuncAttributeMaxDynamicSharedMemorySize, SMEM_TOTAL);
        attr_set = 1;
    }

    convert_qd_kernel<<<1024, NTHREADS>>>(Qg, Dg, out);
    colbert_mma_kernel<<<B_ * (LQ_ / TM), NTHREADS, SMEM_TOTAL>>>(out);
}